// round 12
// baseline (speedup 1.0000x reference)
#include <cuda_runtime.h>
#include <cuda_bf16.h>
#include <mma.h>
#include <math.h>
#include <stdint.h>

using namespace nvcuda;

// Problem constants (fixed by the dataset)
#define BATCH  128
#define TSTEPS 128
#define DIM    1024
#define NCOLS  2048          // [r-block | u-block] output features
#define KP     3072          // packed K' = [hi|hi|lo] x [hi|lo|hi] split GEMM
#define NCHUNK 96            // KP / 32 (precompute)

// Precompute GEMM tiling
#define BM 128
#define BN 64
#define BK 32
#define LDA 40
#define LDB 40
#define ASZ (BM * LDA)
#define BSZ (BN * LDB)

// Scan (persistent) kernel geometry
#define SCAN_CTAS   128      // 32 n-slices x 4 k-slices; also == BATCH for combine
#define SCAN_THREADS 256
#define KSL         4        // k-split factor in scan
#define KSLICE      768      // KP / KSL
#define NSLICE      64
#define LDBP        776      // B-slice smem row stride (bf16 elems)
#define SB_BYTES    (NSLICE * LDBP * 2)           // 99328
#define SA_BYTES    (2 * 128 * LDA * 2)           // 20480 (double buffer)
#define H_OFF       (SB_BYTES + SA_BYTES)         // 119808
#define SCAN_SMEM   (H_OFF + DIM * 4)             // 123904

// ---------------- scratch (device symbols; NEVER passed from host) --------
__device__ float g_FW[(size_t)BATCH * TSTEPS * NCOLS];      // fWr||fW
__device__ float g_part[KSL * BATCH * NCOLS];               // k-split partials
__device__ __align__(16) __nv_bfloat16 g_Af[(size_t)BATCH * TSTEPS * KP];
__device__ __align__(16) __nv_bfloat16 g_Ah[BATCH * KP];
__device__ __align__(16) __nv_bfloat16 g_Bf[(size_t)NCOLS * KP];
__device__ __align__(16) __nv_bfloat16 g_Bu[(size_t)NCOLS * KP];

// software grid barrier state
__device__ int g_bar_arrive;
__device__ volatile int g_bar_gen;

// ---------------- helpers ---------------------------------------------------
__device__ __forceinline__ uint32_t smem_u32(const void* p) {
    uint32_t a;
    asm("{ .reg .u64 t; cvta.to.shared.u64 t, %1; cvt.u32.u64 %0, t; }"
        : "=r"(a) : "l"(p));
    return a;
}

__device__ __forceinline__ void cpasync16(uint32_t dst, const void* src) {
    asm volatile("cp.async.cg.shared.global [%0], [%1], 16;"
                 :: "r"(dst), "l"(src) : "memory");
}

// Grid-wide barrier. EVERY thread fences its own stores (GPU scope) before
// arrival (threadFenceReduction pattern).
__device__ __forceinline__ void grid_barrier() {
    __threadfence();          // all threads: publish my stores GPU-wide
    __syncthreads();
    if (threadIdx.x == 0) {
        int gen = g_bar_gen;
        if (atomicAdd(&g_bar_arrive, 1) == SCAN_CTAS - 1) {
            g_bar_arrive = 0;
            __threadfence();
            g_bar_gen = gen + 1;
        } else {
            while (g_bar_gen == gen) { }
            __threadfence();  // acquire
        }
    }
    __syncthreads();
}

// ---------------------------------------------------------------------------
// Precompute GEMM (round-9, passing): C=g_FW = A'(g_Af) @ B'(g_Bf)^T
// ---------------------------------------------------------------------------
__device__ __forceinline__ void stage_tiles_pre(
    uint32_t sa_base, uint32_t sb_base, int m0, int n0, int kb, int tid) {
#pragma unroll
    for (int i = 0; i < 4; ++i) {
        int v = tid + 128 * i;
        int row = v >> 2, kv = v & 3;
        cpasync16(sa_base + row * (LDA * 2) + kv * 16,
                  g_Af + (size_t)(m0 + row) * KP + kb + kv * 8);
    }
#pragma unroll
    for (int i = 0; i < 2; ++i) {
        int v = tid + 128 * i;
        int row = v >> 2, kv = v & 3;
        cpasync16(sb_base + row * (LDB * 2) + kv * 16,
                  g_Bf + (size_t)(n0 + row) * KP + kb + kv * 8);
    }
    asm volatile("cp.async.commit_group;" ::: "memory");
}

__global__ __launch_bounds__(128) void gemm_pre() {
    __shared__ __align__(16) __nv_bfloat16 sa[2][ASZ];
    __shared__ __align__(16) __nv_bfloat16 sb[2][BSZ];

    const int tid = threadIdx.x, warp = tid >> 5;
    const int wm = warp >> 1, wn = warp & 1;
    const int m0 = blockIdx.y * BM, n0 = blockIdx.x * BN;
    const uint32_t sa0 = smem_u32(&sa[0][0]);
    const uint32_t sb0 = smem_u32(&sb[0][0]);

    wmma::fragment<wmma::accumulator, 16, 16, 16, float> c[4][2];
#pragma unroll
    for (int mt = 0; mt < 4; ++mt)
#pragma unroll
        for (int nt = 0; nt < 2; ++nt) wmma::fill_fragment(c[mt][nt], 0.0f);

    stage_tiles_pre(sa0, sb0, m0, n0, 0, tid);

    for (int kt = 0; kt < NCHUNK; ++kt) {
        if (kt + 1 < NCHUNK) {
            stage_tiles_pre(sa0 + ((kt + 1) & 1) * (ASZ * 2),
                            sb0 + ((kt + 1) & 1) * (BSZ * 2),
                            m0, n0, (kt + 1) * BK, tid);
            asm volatile("cp.async.wait_group 1;" ::: "memory");
        } else {
            asm volatile("cp.async.wait_group 0;" ::: "memory");
        }
        __syncthreads();

        const __nv_bfloat16* pa = &sa[kt & 1][0] + (wm * 64) * LDA;
        const __nv_bfloat16* pb = &sb[kt & 1][0] + (wn * 32) * LDB;
#pragma unroll
        for (int kk = 0; kk < 2; ++kk) {
            wmma::fragment<wmma::matrix_a, 16, 16, 16, __nv_bfloat16,
                           wmma::row_major> af[4];
            wmma::fragment<wmma::matrix_b, 16, 16, 16, __nv_bfloat16,
                           wmma::col_major> bf[2];
#pragma unroll
            for (int mt = 0; mt < 4; ++mt)
                wmma::load_matrix_sync(af[mt], pa + mt * 16 * LDA + kk * 16, LDA);
#pragma unroll
            for (int nt = 0; nt < 2; ++nt)
                wmma::load_matrix_sync(bf[nt], pb + nt * 16 * LDB + kk * 16, LDB);
#pragma unroll
            for (int mt = 0; mt < 4; ++mt)
#pragma unroll
                for (int nt = 0; nt < 2; ++nt)
                    wmma::mma_sync(c[mt][nt], af[mt], bf[nt], c[mt][nt]);
        }
        __syncthreads();
    }

    const size_t crow = (size_t)m0 + wm * 64;
    const int ccol = n0 + wn * 32;
#pragma unroll
    for (int mt = 0; mt < 4; ++mt)
#pragma unroll
        for (int nt = 0; nt < 2; ++nt)
            wmma::store_matrix_sync(g_FW + (crow + mt * 16) * NCOLS + ccol + nt * 16,
                                    c[mt][nt], NCOLS, wmma::mem_row_major);
}

// ---------------------------------------------------------------------------
// Persistent scan kernel: all 128 recurrence steps in ONE launch.
//   CTA c: ni = c&31 (n-slice of 64), ki = c>>5 (k-slice of 768); ALSO owns
//   combine for batch b == c (h state lives in this CTA's smem).
//   B-slice [64 x 768] stays resident in smem for all steps.
// ---------------------------------------------------------------------------
extern __shared__ __align__(16) unsigned char dynsmem[];

__global__ __launch_bounds__(SCAN_THREADS) void scan_kernel(
    const float* __restrict__ gates, const float* __restrict__ Urb,
    const float* __restrict__ Ub, const int* __restrict__ nf,
    const float* __restrict__ mem_old, float* __restrict__ out) {
    __nv_bfloat16* sB = (__nv_bfloat16*)dynsmem;               // [64][LDBP]
    __nv_bfloat16* sA = (__nv_bfloat16*)(dynsmem + SB_BYTES);  // [2][128][LDA]
    float* sh         = (float*)(dynsmem + H_OFF);             // [1024]

    const int tid = threadIdx.x;
    const int cta = blockIdx.x;
    const int ni = cta & 31, ki = cta >> 5;
    const int n0 = ni * NSLICE;
    const int k0 = ki * KSLICE;
    const int warp = tid >> 5;
    const int wm = warp & 3, wn = warp >> 2;   // 4 m-warps x 2 n-warps

    // ---- load resident B slice [64 rows][768 k] ----
    // 768 bf16 per row = 96 x 16B vectors  (round-11 bug: was 48 -> half the
    // slice left uninitialized)
    for (int v = tid; v < NSLICE * 96; v += SCAN_THREADS) {
        int row = v / 96, kv = v % 96;
        *(uint4*)(sB + (size_t)row * LDBP + kv * 8) =
            *(const uint4*)(g_Bu + (size_t)(n0 + row) * KP + k0 + kv * 8);
    }

    // ---- init h (batch b == cta) + biases in registers ----
    float br[4], bu[4];
    const int tout = nf[cta] - 1;
#pragma unroll
    for (int i = 0; i < 4; ++i) {
        int d = tid + i * SCAN_THREADS;
        float v = mem_old[cta * DIM + d];
        sh[d] = v;
        __nv_bfloat16 hi = __float2bfloat16(v);
        __nv_bfloat16 lo = __float2bfloat16(v - __bfloat162float(hi));
        __nv_bfloat16* row = g_Ah + (size_t)cta * KP;
        row[d] = hi; row[1024 + d] = hi; row[2048 + d] = lo;
        br[i] = Urb[d];
        bu[i] = Ub[d];
    }
    grid_barrier();   // g_Ah fully initialized (and published) before GEMM

    const uint32_t sa0 = smem_u32(sA);
    const __nv_bfloat16* Abase = g_Ah + k0;

    for (int t = 0; t < TSTEPS; ++t) {
        // ===== GEMM phase: partial C[128 x 64] over k window =====
        wmma::fragment<wmma::accumulator, 16, 16, 16, float> c[2][2];
#pragma unroll
        for (int mt = 0; mt < 2; ++mt)
#pragma unroll
            for (int nt = 0; nt < 2; ++nt) wmma::fill_fragment(c[mt][nt], 0.0f);

        // stage A chunk 0
        {
#pragma unroll
            for (int i = 0; i < 2; ++i) {
                int v = tid + SCAN_THREADS * i;
                int row = v >> 2, kv = v & 3;
                cpasync16(sa0 + row * (LDA * 2) + kv * 16,
                          Abase + (size_t)row * KP + kv * 8);
            }
            asm volatile("cp.async.commit_group;" ::: "memory");
        }

        for (int kt = 0; kt < KSLICE / 32; ++kt) {       // 24 chunks
            if (kt + 1 < KSLICE / 32) {
                uint32_t dst = sa0 + ((kt + 1) & 1) * (128 * LDA * 2);
                const __nv_bfloat16* src = Abase + (kt + 1) * 32;
#pragma unroll
                for (int i = 0; i < 2; ++i) {
                    int v = tid + SCAN_THREADS * i;
                    int row = v >> 2, kv = v & 3;
                    cpasync16(dst + row * (LDA * 2) + kv * 16,
                              src + (size_t)row * KP + kv * 8);
                }
                asm volatile("cp.async.commit_group;" ::: "memory");
                asm volatile("cp.async.wait_group 1;" ::: "memory");
            } else {
                asm volatile("cp.async.wait_group 0;" ::: "memory");
            }
            __syncthreads();

            const __nv_bfloat16* pa = sA + (kt & 1) * (128 * LDA) + (wm * 32) * LDA;
            const __nv_bfloat16* pb = sB + (size_t)(wn * 32) * LDBP + kt * 32;
#pragma unroll
            for (int kk = 0; kk < 2; ++kk) {
                wmma::fragment<wmma::matrix_a, 16, 16, 16, __nv_bfloat16,
                               wmma::row_major> af[2];
                wmma::fragment<wmma::matrix_b, 16, 16, 16, __nv_bfloat16,
                               wmma::col_major> bf[2];
#pragma unroll
                for (int mt = 0; mt < 2; ++mt)
                    wmma::load_matrix_sync(af[mt], pa + mt * 16 * LDA + kk * 16, LDA);
#pragma unroll
                for (int nt = 0; nt < 2; ++nt)
                    wmma::load_matrix_sync(bf[nt], pb + (size_t)nt * 16 * LDBP + kk * 16,
                                           LDBP);
#pragma unroll
                for (int mt = 0; mt < 2; ++mt)
#pragma unroll
                    for (int nt = 0; nt < 2; ++nt)
                        wmma::mma_sync(c[mt][nt], af[mt], bf[nt], c[mt][nt]);
            }
            __syncthreads();
        }

        // write partials: g_part[ki][m][col]
        {
            float* base = g_part + (size_t)ki * BATCH * NCOLS;
#pragma unroll
            for (int mt = 0; mt < 2; ++mt)
#pragma unroll
                for (int nt = 0; nt < 2; ++nt)
                    wmma::store_matrix_sync(
                        base + (size_t)(wm * 32 + mt * 16) * NCOLS + n0 + wn * 32 + nt * 16,
                        c[mt][nt], NCOLS, wmma::mem_row_major);
        }
        grid_barrier();   // partials published + visible everywhere

        // ===== combine phase: this CTA handles batch b == cta =====
        {
            const float gt = gates[cta * TSTEPS + t];
            const float* fw = g_FW + ((size_t)cta * TSTEPS + t) * NCOLS;
            __nv_bfloat16* row = g_Ah + (size_t)cta * KP;
#pragma unroll
            for (int i = 0; i < 4; ++i) {
                int d = tid + i * SCAN_THREADS;
                const float* pb0 = g_part + (size_t)cta * NCOLS + d;
                float pr = 0.f, pu = 0.f;
#pragma unroll
                for (int s = 0; s < KSL; ++s) {
                    pr += __ldcg(pb0 + (size_t)s * BATCH * NCOLS);
                    pu += __ldcg(pb0 + (size_t)s * BATCH * NCOLS + 1024);
                }
                float xr = fw[d] + pr + br[i];
                float r  = 1.f / (1.f + expf(-xr));
                float ht = tanhf(fw[1024 + d] + r * (pu + bu[i]));
                float hold = sh[d];
                float hn = gt * ht + (1.f - gt) * hold;
                sh[d] = hn;
                __nv_bfloat16 hi = __float2bfloat16(hn);
                __nv_bfloat16 lo = __float2bfloat16(hn - __bfloat162float(hi));
                row[d] = hi; row[1024 + d] = hi; row[2048 + d] = lo;
                if (t == tout) out[cta * DIM + d] = hn;
            }
        }
        grid_barrier();   // repacked h published before next step's GEMM
    }
}

// ---------------------------------------------------------------------------
// packing kernels (round-9 verbatim)
// ---------------------------------------------------------------------------
__global__ void pack_w_kernel(const float* __restrict__ w0,
                              const float* __restrict__ w1, int which) {
    __nv_bfloat16* dst = (which == 0) ? g_Bf : g_Bu;
    size_t i = (size_t)blockIdx.x * blockDim.x + threadIdx.x;
    int n = (int)(i >> 10), k = (int)(i & 1023);
    float v = (n < 1024) ? w0[(size_t)n * 1024 + k] : w1[(size_t)(n - 1024) * 1024 + k];
    __nv_bfloat16 hi = __float2bfloat16(v);
    __nv_bfloat16 lo = __float2bfloat16(v - __bfloat162float(hi));
    __nv_bfloat16* row = dst + (size_t)n * KP;
    row[k] = hi; row[1024 + k] = lo; row[2048 + k] = hi;
}

__global__ void pack_facts_kernel(const float* __restrict__ facts) {
    size_t i = (size_t)blockIdx.x * blockDim.x + threadIdx.x;
    size_t r = i >> 10; int k = (int)(i & 1023);
    float v = facts[i];
    __nv_bfloat16 hi = __float2bfloat16(v);
    __nv_bfloat16 lo = __float2bfloat16(v - __bfloat162float(hi));
    __nv_bfloat16* row = g_Af + r * KP;
    row[k] = hi; row[1024 + k] = hi; row[2048 + k] = lo;
}

// ---------------------------------------------------------------------------
extern "C" void kernel_launch(void* const* d_in, const int* in_sizes, int n_in,
                              void* d_out, int out_size) {
    const float* facts   = (const float*)d_in[0];
    const int*   nf      = (const int*)d_in[1];
    const float* g       = (const float*)d_in[2];
    const float* mem_old = (const float*)d_in[3];
    const float* Wr      = (const float*)d_in[4];
    const float* Urw     = (const float*)d_in[5];
    const float* Urb     = (const float*)d_in[6];
    const float* W       = (const float*)d_in[7];
    const float* Uw      = (const float*)d_in[8];
    const float* Ub      = (const float*)d_in[9];
    float* out = (float*)d_out;

    cudaFuncSetAttribute(scan_kernel,
                         cudaFuncAttributeMaxDynamicSharedMemorySize,
                         SCAN_SMEM);

    pack_w_kernel<<<(2048 * 1024) / 256, 256>>>(Wr, W, /*which=*/0);
    pack_w_kernel<<<(2048 * 1024) / 256, 256>>>(Urw, Uw, /*which=*/1);
    pack_facts_kernel<<<(16384 * 1024) / 256, 256>>>(facts);

    // precompute fWr||fW : [16384, 2048] = A'(facts) @ B'(Wr;W)^T
    gemm_pre<<<dim3(NCOLS / BN, 128, 1), 128>>>();

    // all 128 recurrence steps in one persistent launch
    scan_kernel<<<SCAN_CTAS, SCAN_THREADS, SCAN_SMEM>>>(g, Urb, Ub, nf,
                                                        mem_old, out);
}